// round 1
// baseline (speedup 1.0000x reference)
#include <cuda_runtime.h>
#include <cuda_bf16.h>
#include <math.h>

// Problem constants
#define DK   4096      // d_model
#define NN   128       // E*P rows of prototypes
#define EE   64        // experts
#define TOPK 8
#define SCALE_ 10.0f

// GEMM tile config
#define BM 128
#define BK 16
#define LDA 132        // padded smem row stride (floats), keeps float4 alignment
#define NTHREADS 256

__device__ float g_inv_pnorm[NN];

// ---------------------------------------------------------------------------
// Kernel 1: inverse L2 norms of the 128 prototype rows
// ---------------------------------------------------------------------------
__global__ void pnorm_kernel(const float* __restrict__ proto) {
    int row = blockIdx.x;
    const float4* p = reinterpret_cast<const float4*>(proto + (size_t)row * DK);
    float s = 0.f;
    for (int i = threadIdx.x; i < DK / 4; i += blockDim.x) {
        float4 v = p[i];
        s += v.x * v.x + v.y * v.y + v.z * v.z + v.w * v.w;
    }
    for (int o = 16; o; o >>= 1) s += __shfl_down_sync(0xffffffffu, s, o);
    __shared__ float sm[8];
    if ((threadIdx.x & 31) == 0) sm[threadIdx.x >> 5] = s;
    __syncthreads();
    if (threadIdx.x == 0) {
        float t = 0.f;
        for (int i = 0; i < (int)(blockDim.x >> 5); i++) t += sm[i];
        g_inv_pnorm[row] = 1.0f / (sqrtf(t) + 1e-6f);
    }
}

// ---------------------------------------------------------------------------
// Kernel 2: fused SGEMM (128 tokens x 128 proto rows x 4096) + router epilogue
// ---------------------------------------------------------------------------
extern "C" __global__ void __launch_bounds__(NTHREADS, 1)
router_kernel(const float* __restrict__ h,
              const float* __restrict__ proto,
              float* __restrict__ out,       // [4][T][64]
              int T) {
    extern __shared__ float smem[];
    float* As   = smem;                      // BK*LDA = 2112
    float* Bs   = As + BK * LDA;             // 2112
    float* sims = Bs + BK * LDA;             // 128*LDA = 16896
    float* hsq  = sims + BM * LDA;           // 128*4
    float* invh = hsq + BM * 4;              // 128
    float* invp = invh + BM;                 // 128

    const int tid  = threadIdx.x;
    const int t0   = blockIdx.x * BM;
    const int lrow = tid >> 2;               // 0..63 : gmem load row
    const int lc4  = tid & 3;                // float4 column group within BK
    const int ty   = tid >> 4;               // 0..15
    const int tx   = tid & 15;               // 0..15

    const float* Ab = h + (size_t)t0 * DK;

    float acc[8][8];
#pragma unroll
    for (int i = 0; i < 8; i++)
#pragma unroll
        for (int j = 0; j < 8; j++) acc[i][j] = 0.f;

    float hs0 = 0.f, hs1 = 0.f;
    float4 a0, a1, b0, b1;

    // prefetch tile 0
    {
        int kb = lc4 * 4;
        a0 = *reinterpret_cast<const float4*>(Ab + (size_t)lrow * DK + kb);
        a1 = *reinterpret_cast<const float4*>(Ab + (size_t)(lrow + 64) * DK + kb);
        b0 = *reinterpret_cast<const float4*>(proto + (size_t)lrow * DK + kb);
        b1 = *reinterpret_cast<const float4*>(proto + (size_t)(lrow + 64) * DK + kb);
    }

    const int NT = DK / BK;
    for (int kt = 0; kt < NT; ++kt) {
        // token sum-of-squares (folded normalization)
        hs0 += a0.x * a0.x + a0.y * a0.y + a0.z * a0.z + a0.w * a0.w;
        hs1 += a1.x * a1.x + a1.y * a1.y + a1.z * a1.z + a1.w * a1.w;

        // store tiles transposed [k][m]
        {
            int c = lc4 * 4;
            As[(c + 0) * LDA + lrow] = a0.x;
            As[(c + 1) * LDA + lrow] = a0.y;
            As[(c + 2) * LDA + lrow] = a0.z;
            As[(c + 3) * LDA + lrow] = a0.w;
            As[(c + 0) * LDA + lrow + 64] = a1.x;
            As[(c + 1) * LDA + lrow + 64] = a1.y;
            As[(c + 2) * LDA + lrow + 64] = a1.z;
            As[(c + 3) * LDA + lrow + 64] = a1.w;
            Bs[(c + 0) * LDA + lrow] = b0.x;
            Bs[(c + 1) * LDA + lrow] = b0.y;
            Bs[(c + 2) * LDA + lrow] = b0.z;
            Bs[(c + 3) * LDA + lrow] = b0.w;
            Bs[(c + 0) * LDA + lrow + 64] = b1.x;
            Bs[(c + 1) * LDA + lrow + 64] = b1.y;
            Bs[(c + 2) * LDA + lrow + 64] = b1.z;
            Bs[(c + 3) * LDA + lrow + 64] = b1.w;
        }
        __syncthreads();

        // prefetch next tile into registers (overlaps with compute below)
        if (kt + 1 < NT) {
            int kb = (kt + 1) * BK + lc4 * 4;
            a0 = *reinterpret_cast<const float4*>(Ab + (size_t)lrow * DK + kb);
            a1 = *reinterpret_cast<const float4*>(Ab + (size_t)(lrow + 64) * DK + kb);
            b0 = *reinterpret_cast<const float4*>(proto + (size_t)lrow * DK + kb);
            b1 = *reinterpret_cast<const float4*>(proto + (size_t)(lrow + 64) * DK + kb);
        }

#pragma unroll
        for (int k = 0; k < BK; ++k) {
            float af[8], bf[8];
            float4 t4;
            t4 = *reinterpret_cast<const float4*>(&As[k * LDA + ty * 4]);
            af[0] = t4.x; af[1] = t4.y; af[2] = t4.z; af[3] = t4.w;
            t4 = *reinterpret_cast<const float4*>(&As[k * LDA + 64 + ty * 4]);
            af[4] = t4.x; af[5] = t4.y; af[6] = t4.z; af[7] = t4.w;
            t4 = *reinterpret_cast<const float4*>(&Bs[k * LDA + tx * 4]);
            bf[0] = t4.x; bf[1] = t4.y; bf[2] = t4.z; bf[3] = t4.w;
            t4 = *reinterpret_cast<const float4*>(&Bs[k * LDA + 64 + tx * 4]);
            bf[4] = t4.x; bf[5] = t4.y; bf[6] = t4.z; bf[7] = t4.w;
#pragma unroll
            for (int i = 0; i < 8; i++)
#pragma unroll
                for (int j = 0; j < 8; j++) acc[i][j] += af[i] * bf[j];
        }
        __syncthreads();
    }

    // ---- epilogue ----
    hsq[lrow * 4 + lc4]        = hs0;
    hsq[(lrow + 64) * 4 + lc4] = hs1;
    __syncthreads();
    if (tid < 128) {
        float s = hsq[tid * 4] + hsq[tid * 4 + 1] + hsq[tid * 4 + 2] + hsq[tid * 4 + 3];
        invh[tid] = 1.0f / (sqrtf(s) + 1e-6f);
        invp[tid] = g_inv_pnorm[tid];
    }
    __syncthreads();

    // scaled cosine sims into smem
#pragma unroll
    for (int i = 0; i < 8; i++) {
        int r = (i < 4) ? (ty * 4 + i) : (64 + ty * 4 + i - 4);
        float ih = invh[r];
#pragma unroll
        for (int j = 0; j < 8; j++) {
            int c = (j < 4) ? (tx * 4 + j) : (64 + tx * 4 + j - 4);
            sims[r * LDA + c] = acc[i][j] * ih * invp[c];
        }
    }
    __syncthreads();

    // per-token router: 8 warps, each processes 16 rows
    const int warp = tid >> 5, lane = tid & 31;
    float* out_mask = out;
    float* out_prob = out + (size_t)T * EE;
    float* out_lc   = out + (size_t)2 * T * EE;
    float* out_ls   = out + (size_t)3 * T * EE;

    for (int r = warp; r < BM; r += 8) {
        const float* srow = &sims[r * LDA];
        // logsumexp over P=2 per expert; lane owns experts lane and lane+32
        float l0, l1;
        {
            float s0 = srow[2 * lane], s1 = srow[2 * lane + 1];
            float m = fmaxf(s0, s1);
            l0 = SCALE_ * (m + logf(expf(s0 - m) + expf(s1 - m)));
            s0 = srow[64 + 2 * lane]; s1 = srow[64 + 2 * lane + 1];
            m = fmaxf(s0, s1);
            l1 = SCALE_ * (m + logf(expf(s0 - m) + expf(s1 - m)));
        }

        bool sel0 = false, sel1 = false;
        float mx = -INFINITY;
#pragma unroll
        for (int it = 0; it < TOPK; ++it) {
            float v0 = sel0 ? -INFINITY : l0;
            float v1 = sel1 ? -INFINITY : l1;
            float v; int idx;
            if (v0 >= v1) { v = v0; idx = lane; }
            else          { v = v1; idx = lane + 32; }
            for (int o = 16; o; o >>= 1) {
                float ov = __shfl_down_sync(0xffffffffu, v, o);
                int   oi = __shfl_down_sync(0xffffffffu, idx, o);
                if (ov > v || (ov == v && oi < idx)) { v = ov; idx = oi; }
            }
            int   w  = __shfl_sync(0xffffffffu, idx, 0);
            float wv = __shfl_sync(0xffffffffu, v, 0);
            if (it == 0) mx = wv;
            if (w == lane)           sel0 = true;
            else if (w == lane + 32) sel1 = true;
        }

        // stable dense softmax + masked renorm
        float z0 = expf(l0 - mx), z1 = expf(l1 - mx);
        float zs = z0 + z1;
        for (int o = 16; o; o >>= 1) zs += __shfl_xor_sync(0xffffffffu, zs, o);
        float d0 = z0 / zs, d1 = z1 / zs;
        float ms = (sel0 ? d0 : 0.f) + (sel1 ? d1 : 0.f);
        for (int o = 16; o; o >>= 1) ms += __shfl_xor_sync(0xffffffffu, ms, o);
        float inv = 1.0f / (ms + 1e-9f);
        float p0 = sel0 ? d0 * inv : 0.f;
        float p1 = sel1 ? d1 * inv : 0.f;

        size_t base = (size_t)(t0 + r) * EE;
        out_mask[base + lane]      = sel0 ? 1.f : 0.f;
        out_mask[base + lane + 32] = sel1 ? 1.f : 0.f;
        out_prob[base + lane]      = p0;
        out_prob[base + lane + 32] = p1;
        out_lc[base + lane]        = l0;
        out_lc[base + lane + 32]   = l1;
        out_ls[base + lane]        = l0;   // t_sel = 1.0 -> identical
        out_ls[base + lane + 32]   = l1;
    }
}

// ---------------------------------------------------------------------------
extern "C" void kernel_launch(void* const* d_in, const int* in_sizes, int n_in,
                              void* d_out, int out_size) {
    const float* h     = (const float*)d_in[0];
    const float* proto = (const float*)d_in[1];
    float* out = (float*)d_out;
    int T = in_sizes[0] / DK;   // 16384

    pnorm_kernel<<<NN, 256>>>(proto);

    size_t smem_bytes = (size_t)(BK * LDA * 2 + BM * LDA + BM * 4 + 2 * BM) * sizeof(float);
    static bool attr_set = false;
    if (!attr_set) {
        cudaFuncSetAttribute(router_kernel,
                             cudaFuncAttributeMaxDynamicSharedMemorySize,
                             (int)smem_bytes);
        attr_set = true;
    }
    router_kernel<<<T / BM, NTHREADS, smem_bytes>>>(h, proto, out, T);
}

// round 3
// speedup vs baseline: 1.3311x; 1.3311x over previous
#include <cuda_runtime.h>
#include <math.h>
#include <stdint.h>

// ---------------- problem constants ----------------
#define DK   4096
#define EE   64
#define TOPK 8
#define BM   128
#define BN   128
#define CHUNK 16                 // K floats per stage
#define NCHUNK (DK/CHUNK)        // 256
#define NTHREADS 256

// ---------------- smem layout (bytes) ----------------
#define TILEB   4096             // 128 rows x 32 bytes (16 bf16) per tile
#define STAGEB  (6*TILEB)        // A1,A2,A3,B1,B2,B3 = 24576
#define OFF_SIMS (2*STAGEB)      // 49152
#define LDS_ 132
#define OFF_HSQ  (OFF_SIMS + 128*LDS_*4)   // 116736
#define OFF_INVH (OFF_HSQ + 256*4)         // 117760
#define OFF_INVP (OFF_INVH + 128*4)        // 118272
#define SMEM_TOTAL (OFF_INVP + 128*4)      // 118784

__device__ float g_inv_pnorm[BN];

// ---------------- helpers ----------------
__device__ __forceinline__ uint32_t smem_u32(const void* p) {
    uint32_t a;
    asm("{ .reg .u64 t; cvta.to.shared.u64 t, %1; cvt.u32.u64 %0, t; }" : "=r"(a) : "l"(p));
    return a;
}

__device__ __forceinline__ void ldm4(uint32_t* r, uint32_t addr) {
    asm volatile("ldmatrix.sync.aligned.m8n8.x4.shared.b16 {%0,%1,%2,%3}, [%4];"
        : "=r"(r[0]), "=r"(r[1]), "=r"(r[2]), "=r"(r[3]) : "r"(addr));
}

__device__ __forceinline__ void mma16816(float* c, const uint32_t* a, uint32_t b0, uint32_t b1) {
    asm volatile("mma.sync.aligned.m16n8k16.row.col.f32.bf16.bf16.f32 "
        "{%0,%1,%2,%3}, {%4,%5,%6,%7}, {%8,%9}, {%0,%1,%2,%3};"
        : "+f"(c[0]), "+f"(c[1]), "+f"(c[2]), "+f"(c[3])
        : "r"(a[0]), "r"(a[1]), "r"(a[2]), "r"(a[3]), "r"(b0), "r"(b1));
}

// 3-way bf16 split of a float pair (x = even k, y = odd k)
__device__ __forceinline__ void split3(float x, float y,
                                       uint32_t& u1, uint32_t& u2, uint32_t& u3) {
    asm("cvt.rn.bf16x2.f32 %0, %1, %2;" : "=r"(u1) : "f"(y), "f"(x));
    float rx = x - __uint_as_float(u1 << 16);
    float ry = y - __uint_as_float(u1 & 0xffff0000u);
    asm("cvt.rn.bf16x2.f32 %0, %1, %2;" : "=r"(u2) : "f"(ry), "f"(rx));
    rx -= __uint_as_float(u2 << 16);
    ry -= __uint_as_float(u2 & 0xffff0000u);
    asm("cvt.rn.bf16x2.f32 %0, %1, %2;" : "=r"(u3) : "f"(ry), "f"(rx));
}

// ---------------------------------------------------------------------------
// Kernel 1: inverse L2 norms of the 128 prototype rows
// ---------------------------------------------------------------------------
__global__ void pnorm_kernel(const float* __restrict__ proto) {
    int row = blockIdx.x;
    const float4* p = reinterpret_cast<const float4*>(proto + (size_t)row * DK);
    float s = 0.f;
    for (int i = threadIdx.x; i < DK / 4; i += blockDim.x) {
        float4 v = p[i];
        s += v.x * v.x + v.y * v.y + v.z * v.z + v.w * v.w;
    }
    for (int o = 16; o; o >>= 1) s += __shfl_down_sync(0xffffffffu, s, o);
    __shared__ float sm[8];
    if ((threadIdx.x & 31) == 0) sm[threadIdx.x >> 5] = s;
    __syncthreads();
    if (threadIdx.x == 0) {
        float t = 0.f;
        for (int i = 0; i < (int)(blockDim.x >> 5); i++) t += sm[i];
        g_inv_pnorm[row] = 1.0f / (sqrtf(t) + 1e-6f);
    }
}

// ---------------------------------------------------------------------------
// Kernel 2: 6-pass split-bf16 mma.sync GEMM (128x128x4096) + router epilogue
// ---------------------------------------------------------------------------
extern "C" __global__ void __launch_bounds__(NTHREADS, 1)
router_mma(const float* __restrict__ h, const float* __restrict__ proto,
           float* __restrict__ out, int T) {
    extern __shared__ char smem[];
    const uint32_t smem_u = smem_u32(smem);
    const int tid  = threadIdx.x;
    const int wid  = tid >> 5;
    const int lane = tid & 31;
    const int t0   = blockIdx.x * BM;

    if (tid < BN) ((float*)(smem + OFF_INVP))[tid] = g_inv_pnorm[tid];

    // global load mapping: thread -> row r = tid>>1, half = tid&1 (8 floats)
    const int r    = tid >> 1;
    const int half = tid & 1;
    const float* ag = h     + (size_t)(t0 + r) * DK + half * 8;
    const float* bg = proto + (size_t)r        * DK + half * 8;

    // swizzled store offset: row*32 + ((half ^ ((row>>2)&1))*16)
    const uint32_t st_off = (uint32_t)r * 32u + (uint32_t)((half ^ ((r >> 2) & 1)) * 16);

    // warp tile: 64 (M) x 32 (N)
    const int warp_m = (wid >> 2) * 64;
    const int warp_n = (wid & 3) * 32;

    // ldmatrix lane offsets (within a tile)
    uint32_t aoff[4], boff[2];
#pragma unroll
    for (int mi = 0; mi < 4; mi++) {
        int arow = warp_m + mi * 16 + ((lane >> 3) & 1) * 8 + (lane & 7);
        int kh   = lane >> 4;
        aoff[mi] = (uint32_t)arow * 32u + (uint32_t)((kh ^ ((arow >> 2) & 1)) * 16);
    }
#pragma unroll
    for (int n16 = 0; n16 < 2; n16++) {
        int brow = warp_n + n16 * 16 + ((lane >> 4) & 1) * 8 + (lane & 7);
        int kh   = (lane >> 3) & 1;
        boff[n16] = (uint32_t)brow * 32u + (uint32_t)((kh ^ ((brow >> 2) & 1)) * 16);
    }

    float acc[4][4][4];
#pragma unroll
    for (int a = 0; a < 4; a++)
#pragma unroll
        for (int b = 0; b < 4; b++)
#pragma unroll
            for (int c = 0; c < 4; c++) acc[a][b][c] = 0.f;

    float4 av[2], bv[2];
    av[0] = ((const float4*)ag)[0]; av[1] = ((const float4*)ag)[1];
    bv[0] = ((const float4*)bg)[0]; bv[1] = ((const float4*)bg)[1];

    float hsum = 0.f;

    for (int kt = 0; kt < NCHUNK; ++kt) {
        char* stg = smem + (kt & 1) * STAGEB;

        // ---- convert + store (3-way split) ----
        {
            uint32_t w1[4], w2[4], w3[4];
            split3(av[0].x, av[0].y, w1[0], w2[0], w3[0]);
            split3(av[0].z, av[0].w, w1[1], w2[1], w3[1]);
            split3(av[1].x, av[1].y, w1[2], w2[2], w3[2]);
            split3(av[1].z, av[1].w, w1[3], w2[3], w3[3]);
            hsum += av[0].x * av[0].x + av[0].y * av[0].y + av[0].z * av[0].z + av[0].w * av[0].w
                  + av[1].x * av[1].x + av[1].y * av[1].y + av[1].z * av[1].z + av[1].w * av[1].w;
            *(uint4*)(stg + 0 * TILEB + st_off) = make_uint4(w1[0], w1[1], w1[2], w1[3]);
            *(uint4*)(stg + 1 * TILEB + st_off) = make_uint4(w2[0], w2[1], w2[2], w2[3]);
            *(uint4*)(stg + 2 * TILEB + st_off) = make_uint4(w3[0], w3[1], w3[2], w3[3]);

            split3(bv[0].x, bv[0].y, w1[0], w2[0], w3[0]);
            split3(bv[0].z, bv[0].w, w1[1], w2[1], w3[1]);
            split3(bv[1].x, bv[1].y, w1[2], w2[2], w3[2]);
            split3(bv[1].z, bv[1].w, w1[3], w2[3], w3[3]);
            *(uint4*)(stg + 3 * TILEB + st_off) = make_uint4(w1[0], w1[1], w1[2], w1[3]);
            *(uint4*)(stg + 4 * TILEB + st_off) = make_uint4(w2[0], w2[1], w2[2], w2[3]);
            *(uint4*)(stg + 5 * TILEB + st_off) = make_uint4(w3[0], w3[1], w3[2], w3[3]);
        }

        // prefetch next chunk
        if (kt + 1 < NCHUNK) {
            const float* a2 = ag + (size_t)(kt + 1) * CHUNK;
            const float* b2 = bg + (size_t)(kt + 1) * CHUNK;
            av[0] = ((const float4*)a2)[0]; av[1] = ((const float4*)a2)[1];
            bv[0] = ((const float4*)b2)[0]; bv[1] = ((const float4*)b2)[1];
        }

        __syncthreads();

        // ---- MMA: pairs (0,0),(0,1),(0,2),(1,0),(1,1),(2,0) ----
        const uint32_t base = smem_u + (kt & 1) * STAGEB;
#pragma unroll
        for (int i = 0; i < 3; i++) {
            uint32_t A[4][4];
#pragma unroll
            for (int mi = 0; mi < 4; mi++)
                ldm4(A[mi], base + i * TILEB + aoff[mi]);
#pragma unroll
            for (int j = 0; j < 3; j++) {
                if (j < 3 - i) {
                    uint32_t Bf[2][4];
                    ldm4(Bf[0], base + (3 + j) * TILEB + boff[0]);
                    ldm4(Bf[1], base + (3 + j) * TILEB + boff[1]);
#pragma unroll
                    for (int mi = 0; mi < 4; mi++) {
                        mma16816(acc[mi][0], A[mi], Bf[0][0], Bf[0][1]);
                        mma16816(acc[mi][1], A[mi], Bf[0][2], Bf[0][3]);
                        mma16816(acc[mi][2], A[mi], Bf[1][0], Bf[1][1]);
                        mma16816(acc[mi][3], A[mi], Bf[1][2], Bf[1][3]);
                    }
                }
            }
        }
        // single sync per stage: next store targets the other buffer
    }
    __syncthreads();

    // ---- norms ----
    ((float*)(smem + OFF_HSQ))[tid] = hsum;
    __syncthreads();
    if (tid < BM) {
        const float* hsq = (const float*)(smem + OFF_HSQ);
        float s = hsq[2 * tid] + hsq[2 * tid + 1];
        ((float*)(smem + OFF_INVH))[tid] = 1.0f / (sqrtf(s) + 1e-6f);
    }
    __syncthreads();

    // ---- accumulators -> scaled cosine sims in smem ----
    {
        const float* invh = (const float*)(smem + OFF_INVH);
        const float* invp = (const float*)(smem + OFF_INVP);
        float* sims = (float*)(smem + OFF_SIMS);
        int lr = lane >> 2, lc = (lane & 3) * 2;
#pragma unroll
        for (int mi = 0; mi < 4; mi++) {
            int row = warp_m + mi * 16 + lr;
            float ih0 = invh[row], ih1 = invh[row + 8];
#pragma unroll
            for (int nf = 0; nf < 4; nf++) {
                int col = warp_n + nf * 8 + lc;
                float ip0 = invp[col], ip1 = invp[col + 1];
                sims[row * LDS_ + col]           = acc[mi][nf][0] * ih0 * ip0;
                sims[row * LDS_ + col + 1]       = acc[mi][nf][1] * ih0 * ip1;
                sims[(row + 8) * LDS_ + col]     = acc[mi][nf][2] * ih1 * ip0;
                sims[(row + 8) * LDS_ + col + 1] = acc[mi][nf][3] * ih1 * ip1;
            }
        }
    }
    __syncthreads();

    // ---- per-token router: 8 warps, 16 rows each ----
    const float* sims = (const float*)(smem + OFF_SIMS);
    float* out_mask = out;
    float* out_prob = out + (size_t)T * EE;
    float* out_lc   = out + (size_t)2 * T * EE;
    float* out_ls   = out + (size_t)3 * T * EE;

    for (int rr = wid; rr < BM; rr += 8) {
        const float* srow = &sims[rr * LDS_];
        float l0, l1;
        {
            float s0 = srow[2 * lane], s1 = srow[2 * lane + 1];
            float m = fmaxf(s0, s1);
            l0 = 10.0f * (m + logf(expf(s0 - m) + expf(s1 - m)));
            s0 = srow[64 + 2 * lane]; s1 = srow[64 + 2 * lane + 1];
            m = fmaxf(s0, s1);
            l1 = 10.0f * (m + logf(expf(s0 - m) + expf(s1 - m)));
        }

        bool sel0 = false, sel1 = false;
        float mx = -INFINITY;
#pragma unroll
        for (int it = 0; it < TOPK; ++it) {
            float v0 = sel0 ? -INFINITY : l0;
            float v1 = sel1 ? -INFINITY : l1;
            float v; int idx;
            if (v0 >= v1) { v = v0; idx = lane; }
            else          { v = v1; idx = lane + 32; }
            for (int o = 16; o; o >>= 1) {
                float ov = __shfl_down_sync(0xffffffffu, v, o);
                int   oi = __shfl_down_sync(0xffffffffu, idx, o);
                if (ov > v || (ov == v && oi < idx)) { v = ov; idx = oi; }
            }
            int   w  = __shfl_sync(0xffffffffu, idx, 0);
            float wv = __shfl_sync(0xffffffffu, v, 0);
            if (it == 0) mx = wv;
            if (w == lane)           sel0 = true;
            else if (w == lane + 32) sel1 = true;
        }

        float z0 = expf(l0 - mx), z1 = expf(l1 - mx);
        float zs = z0 + z1;
        for (int o = 16; o; o >>= 1) zs += __shfl_xor_sync(0xffffffffu, zs, o);
        float d0 = z0 / zs, d1 = z1 / zs;
        float ms = (sel0 ? d0 : 0.f) + (sel1 ? d1 : 0.f);
        for (int o = 16; o; o >>= 1) ms += __shfl_xor_sync(0xffffffffu, ms, o);
        float inv = 1.0f / (ms + 1e-9f);
        float p0 = sel0 ? d0 * inv : 0.f;
        float p1 = sel1 ? d1 * inv : 0.f;

        size_t bb = (size_t)(t0 + rr) * EE;
        out_mask[bb + lane]      = sel0 ? 1.f : 0.f;
        out_mask[bb + lane + 32] = sel1 ? 1.f : 0.f;
        out_prob[bb + lane]      = p0;
        out_prob[bb + lane + 32] = p1;
        out_lc[bb + lane]        = l0;
        out_lc[bb + lane + 32]   = l1;
        out_ls[bb + lane]        = l0;
        out_ls[bb + lane + 32]   = l1;
    }
}

// ---------------------------------------------------------------------------
extern "C" void kernel_launch(void* const* d_in, const int* in_sizes, int n_in,
                              void* d_out, int out_size) {
    const float* h     = (const float*)d_in[0];
    const float* proto = (const float*)d_in[1];
    float* out = (float*)d_out;
    int T = in_sizes[0] / DK;   // 16384

    pnorm_kernel<<<BN, 256>>>(proto);

    static bool attr_set = false;
    if (!attr_set) {
        cudaFuncSetAttribute(router_mma,
                             cudaFuncAttributeMaxDynamicSharedMemorySize,
                             SMEM_TOTAL);
        attr_set = true;
    }
    router_mma<<<T / BM, NTHREADS, SMEM_TOTAL>>>(h, proto, out, T);
}

// round 4
// speedup vs baseline: 1.8437x; 1.3851x over previous
#include <cuda_runtime.h>
#include <cuda_fp16.h>
#include <math.h>
#include <stdint.h>

// ---------------- problem constants ----------------
#define DK   4096
#define EE   64
#define TOPK 8
#define BM   128
#define BN   128
#define CHUNK 16
#define NCHUNK 256
#define NTHREADS 256

// ---------------- smem layout (bytes) ----------------
#define PLANEB 4096              // 128 rows x 32 bytes (16 f16)
#define STAGEB (2*PLANEB)        // A_hi, A_lo
#define OFF_SIMS (2*STAGEB)      // 16384
#define LDS_ 132
#define OFF_HSQ  (OFF_SIMS + 128*LDS_*4)
#define OFF_INVH (OFF_HSQ + 256*4)
#define OFF_INVP (OFF_INVH + 128*4)
#define SMEM_TOTAL (OFF_INVP + 128*4)

__device__ float g_inv_pnorm[BN];
// B fragments: [kt][pass][n16][lane] -> uint4 (mma matrices 0..3)
__device__ uint4 g_bfrag[NCHUNK * 2 * 8 * 32];

// ---------------- helpers ----------------
__device__ __forceinline__ uint32_t smem_u32(const void* p) {
    uint32_t a;
    asm("{ .reg .u64 t; cvta.to.shared.u64 t, %1; cvt.u32.u64 %0, t; }" : "=r"(a) : "l"(p));
    return a;
}
__device__ __forceinline__ void ldm4(uint32_t* r, uint32_t addr) {
    asm volatile("ldmatrix.sync.aligned.m8n8.x4.shared.b16 {%0,%1,%2,%3}, [%4];"
        : "=r"(r[0]), "=r"(r[1]), "=r"(r[2]), "=r"(r[3]) : "r"(addr));
}
__device__ __forceinline__ void mma16816(float* c, const uint32_t* a, uint32_t b0, uint32_t b1) {
    asm volatile("mma.sync.aligned.m16n8k16.row.col.f32.f16.f16.f32 "
        "{%0,%1,%2,%3}, {%4,%5,%6,%7}, {%8,%9}, {%0,%1,%2,%3};"
        : "+f"(c[0]), "+f"(c[1]), "+f"(c[2]), "+f"(c[3])
        : "r"(a[0]), "r"(a[1]), "r"(a[2]), "r"(a[3]), "r"(b0), "r"(b1));
}
// 2-way fp16 split of a float pair (x = even k -> low half, y = odd k -> high half)
__device__ __forceinline__ void split2(float x, float y, uint32_t& uh, uint32_t& ul) {
    asm("cvt.rn.f16x2.f32 %0, %1, %2;" : "=r"(uh) : "f"(y), "f"(x));
    float lx = __half2float(__ushort_as_half((unsigned short)(uh & 0xffffu)));
    float ly = __half2float(__ushort_as_half((unsigned short)(uh >> 16)));
    float rx = x - lx, ry = y - ly;
    asm("cvt.rn.f16x2.f32 %0, %1, %2;" : "=r"(ul) : "f"(ry), "f"(rx));
}

// ---------------------------------------------------------------------------
// Kernel 1: inverse L2 norms of the 128 prototype rows
// ---------------------------------------------------------------------------
__global__ void pnorm_kernel(const float* __restrict__ proto) {
    int row = blockIdx.x;
    const float4* p = reinterpret_cast<const float4*>(proto + (size_t)row * DK);
    float s = 0.f;
    for (int i = threadIdx.x; i < DK / 4; i += blockDim.x) {
        float4 v = p[i];
        s += v.x * v.x + v.y * v.y + v.z * v.z + v.w * v.w;
    }
    for (int o = 16; o; o >>= 1) s += __shfl_down_sync(0xffffffffu, s, o);
    __shared__ float sm[8];
    if ((threadIdx.x & 31) == 0) sm[threadIdx.x >> 5] = s;
    __syncthreads();
    if (threadIdx.x == 0) {
        float t = 0.f;
        for (int i = 0; i < (int)(blockDim.x >> 5); i++) t += sm[i];
        g_inv_pnorm[row] = 1.0f / (sqrtf(t) + 1e-6f);
    }
}

// ---------------------------------------------------------------------------
// Kernel 2: pre-split proto into fp16 hi/lo, stored in mma B-fragment layout
// ---------------------------------------------------------------------------
__global__ void bsplit_kernel(const float* __restrict__ proto) {
    int idx  = blockIdx.x * blockDim.x + threadIdx.x;  // 131072 total
    int lane = idx & 31;
    int n16  = (idx >> 5) & 7;
    int pass = (idx >> 8) & 1;
    int kt   = idx >> 9;
    uint32_t w[4];
#pragma unroll
    for (int r = 0; r < 4; r++) {
        int n  = n16 * 16 + ((r & 2) << 2) + (lane >> 2);
        int k0 = kt * 16 + (r & 1) * 8 + 2 * (lane & 3);
        float x = proto[(size_t)n * DK + k0];
        float y = proto[(size_t)n * DK + k0 + 1];
        uint32_t uh, ul;
        split2(x, y, uh, ul);
        w[r] = pass ? ul : uh;
    }
    g_bfrag[idx] = make_uint4(w[0], w[1], w[2], w[3]);
}

// ---------------------------------------------------------------------------
// Kernel 3: 3-pass split-fp16 mma.sync GEMM (128x128x4096) + router epilogue
// ---------------------------------------------------------------------------
extern "C" __global__ void __launch_bounds__(NTHREADS, 1)
router_mma(const float* __restrict__ h, const float* __restrict__ proto,
           float* __restrict__ out, int T) {
    extern __shared__ char smem[];
    const uint32_t smem_u = smem_u32(smem);
    const int tid  = threadIdx.x;
    const int wid  = tid >> 5;
    const int lane = tid & 31;
    const int t0   = blockIdx.x * BM;

    if (tid < BN) ((float*)(smem + OFF_INVP))[tid] = g_inv_pnorm[tid];

    // global A load mapping: thread -> row r = tid>>1, half = tid&1 (8 floats)
    const int r    = tid >> 1;
    const int half = tid & 1;
    const float* ag = h + (size_t)(t0 + r) * DK + half * 8;
    const uint32_t st_off = (uint32_t)r * 32u + (uint32_t)((half ^ ((r >> 2) & 1)) * 16);

    // warp tile: 64 (M) x 32 (N)
    const int warp_m  = (wid >> 2) * 64;
    const int warp_n4 = (wid & 3) * 2;   // n16 tile base index

    uint32_t aoff[4];
#pragma unroll
    for (int mi = 0; mi < 4; mi++) {
        int arow = warp_m + mi * 16 + ((lane >> 3) & 1) * 8 + (lane & 7);
        int kh   = lane >> 4;
        aoff[mi] = (uint32_t)arow * 32u + (uint32_t)((kh ^ ((arow >> 2) & 1)) * 16);
    }

    float acc[4][4][4];
#pragma unroll
    for (int a = 0; a < 4; a++)
#pragma unroll
        for (int b = 0; b < 4; b++)
#pragma unroll
            for (int c = 0; c < 4; c++) acc[a][b][c] = 0.f;

    // ---- prologue ----
    float4 av[2];
    av[0] = ((const float4*)ag)[0]; av[1] = ((const float4*)ag)[1];
    float hsum = 0.f;
    {   // convert chunk 0 -> buffer 0
        uint32_t uh[4], ul[4];
        split2(av[0].x, av[0].y, uh[0], ul[0]);
        split2(av[0].z, av[0].w, uh[1], ul[1]);
        split2(av[1].x, av[1].y, uh[2], ul[2]);
        split2(av[1].z, av[1].w, uh[3], ul[3]);
        hsum += av[0].x*av[0].x + av[0].y*av[0].y + av[0].z*av[0].z + av[0].w*av[0].w
              + av[1].x*av[1].x + av[1].y*av[1].y + av[1].z*av[1].z + av[1].w*av[1].w;
        *(uint4*)(smem + st_off)          = make_uint4(uh[0], uh[1], uh[2], uh[3]);
        *(uint4*)(smem + PLANEB + st_off) = make_uint4(ul[0], ul[1], ul[2], ul[3]);
        av[0] = ((const float4*)(ag + CHUNK))[0];
        av[1] = ((const float4*)(ag + CHUNK))[1];
    }
    uint4 bf[2][4];
    {   // B frags for stage 0: [pass][tile]
#pragma unroll
        for (int p = 0; p < 2; p++)
#pragma unroll
            for (int t = 0; t < 2; t++)
                bf[0][p * 2 + t] = g_bfrag[((size_t)(0 * 2 + p) * 8 + warp_n4 + t) * 32 + lane];
    }

    // ---- main loop: one sync per stage, convert/LDG interleaved with MMAs ----
#pragma unroll 2
    for (int kt = 0; kt < NCHUNK; ++kt) {
        __syncthreads();
        const int cb = kt & 1;
        const uint32_t abase = smem_u + cb * STAGEB;

        uint32_t A[4][4];
#pragma unroll
        for (int mi = 0; mi < 4; mi++) ldm4(A[mi], abase + aoff[mi]);

        uint4 b00 = bf[cb][0], b01 = bf[cb][1];   // B_hi tiles
        uint4 b10 = bf[cb][2], b11 = bf[cb][3];   // B_lo tiles

        // pass 1: A_hi x B_hi
#pragma unroll
        for (int mi = 0; mi < 4; mi++) {
            mma16816(acc[mi][0], A[mi], b00.x, b00.y);
            mma16816(acc[mi][1], A[mi], b00.z, b00.w);
            mma16816(acc[mi][2], A[mi], b01.x, b01.y);
            mma16816(acc[mi][3], A[mi], b01.z, b01.w);
        }

        // convert + store chunk kt+1 into the other buffer (overlaps MMA drain)
        if (kt + 1 < NCHUNK) {
            char* stg = smem + (cb ^ 1) * STAGEB;
            uint32_t uh[4], ul[4];
            split2(av[0].x, av[0].y, uh[0], ul[0]);
            split2(av[0].z, av[0].w, uh[1], ul[1]);
            split2(av[1].x, av[1].y, uh[2], ul[2]);
            split2(av[1].z, av[1].w, uh[3], ul[3]);
            hsum += av[0].x*av[0].x + av[0].y*av[0].y + av[0].z*av[0].z + av[0].w*av[0].w
                  + av[1].x*av[1].x + av[1].y*av[1].y + av[1].z*av[1].z + av[1].w*av[1].w;
            *(uint4*)(stg + st_off)          = make_uint4(uh[0], uh[1], uh[2], uh[3]);
            *(uint4*)(stg + PLANEB + st_off) = make_uint4(ul[0], ul[1], ul[2], ul[3]);
        }

        // pass 2: A_hi x B_lo
#pragma unroll
        for (int mi = 0; mi < 4; mi++) {
            mma16816(acc[mi][0], A[mi], b10.x, b10.y);
            mma16816(acc[mi][1], A[mi], b10.z, b10.w);
            mma16816(acc[mi][2], A[mi], b11.x, b11.y);
            mma16816(acc[mi][3], A[mi], b11.z, b11.w);
        }

        // A_lo fragments (reuse regs)
#pragma unroll
        for (int mi = 0; mi < 4; mi++) ldm4(A[mi], abase + PLANEB + aoff[mi]);

        // prefetch: A chunk kt+2, B frags kt+1 (into other reg set)
        {
            int ka = (kt + 2 < NCHUNK) ? kt + 2 : NCHUNK - 1;
            av[0] = ((const float4*)(ag + (size_t)ka * CHUNK))[0];
            av[1] = ((const float4*)(ag + (size_t)ka * CHUNK))[1];
            int kf = (kt + 1 < NCHUNK) ? kt + 1 : NCHUNK - 1;
#pragma unroll
            for (int p = 0; p < 2; p++)
#pragma unroll
                for (int t = 0; t < 2; t++)
                    bf[cb ^ 1][p * 2 + t] =
                        g_bfrag[((size_t)(kf * 2 + p) * 8 + warp_n4 + t) * 32 + lane];
        }

        // pass 3: A_lo x B_hi
#pragma unroll
        for (int mi = 0; mi < 4; mi++) {
            mma16816(acc[mi][0], A[mi], b00.x, b00.y);
            mma16816(acc[mi][1], A[mi], b00.z, b00.w);
            mma16816(acc[mi][2], A[mi], b01.x, b01.y);
            mma16816(acc[mi][3], A[mi], b01.z, b01.w);
        }
    }
    __syncthreads();

    // ---- norms ----
    ((float*)(smem + OFF_HSQ))[tid] = hsum;
    __syncthreads();
    if (tid < BM) {
        const float* hsq = (const float*)(smem + OFF_HSQ);
        float s = hsq[2 * tid] + hsq[2 * tid + 1];
        ((float*)(smem + OFF_INVH))[tid] = 1.0f / (sqrtf(s) + 1e-6f);
    }
    __syncthreads();

    // ---- accumulators -> scaled cosine sims in smem ----
    {
        const float* invh = (const float*)(smem + OFF_INVH);
        const float* invp = (const float*)(smem + OFF_INVP);
        float* sims = (float*)(smem + OFF_SIMS);
        const int warp_n = (wid & 3) * 32;
        int lr = lane >> 2, lc = (lane & 3) * 2;
#pragma unroll
        for (int mi = 0; mi < 4; mi++) {
            int row = warp_m + mi * 16 + lr;
            float ih0 = invh[row], ih1 = invh[row + 8];
#pragma unroll
            for (int nf = 0; nf < 4; nf++) {
                int col = warp_n + nf * 8 + lc;
                float ip0 = invp[col], ip1 = invp[col + 1];
                sims[row * LDS_ + col]           = acc[mi][nf][0] * ih0 * ip0;
                sims[row * LDS_ + col + 1]       = acc[mi][nf][1] * ih0 * ip1;
                sims[(row + 8) * LDS_ + col]     = acc[mi][nf][2] * ih1 * ip0;
                sims[(row + 8) * LDS_ + col + 1] = acc[mi][nf][3] * ih1 * ip1;
            }
        }
    }
    __syncthreads();

    // ---- per-token router: 8 warps, 16 rows each ----
    const float* sims = (const float*)(smem + OFF_SIMS);
    float* out_mask = out;
    float* out_prob = out + (size_t)T * EE;
    float* out_lc   = out + (size_t)2 * T * EE;
    float* out_ls   = out + (size_t)3 * T * EE;

    for (int rr = wid; rr < BM; rr += 8) {
        const float* srow = &sims[rr * LDS_];
        float l0, l1;
        {
            float s0 = srow[2 * lane], s1 = srow[2 * lane + 1];
            float m = fmaxf(s0, s1);
            l0 = 10.0f * (m + logf(expf(s0 - m) + expf(s1 - m)));
            s0 = srow[64 + 2 * lane]; s1 = srow[64 + 2 * lane + 1];
            m = fmaxf(s0, s1);
            l1 = 10.0f * (m + logf(expf(s0 - m) + expf(s1 - m)));
        }

        bool sel0 = false, sel1 = false;
        float mx = -INFINITY;
#pragma unroll
        for (int it = 0; it < TOPK; ++it) {
            float v0 = sel0 ? -INFINITY : l0;
            float v1 = sel1 ? -INFINITY : l1;
            float v; int idx;
            if (v0 >= v1) { v = v0; idx = lane; }
            else          { v = v1; idx = lane + 32; }
            for (int o = 16; o; o >>= 1) {
                float ov = __shfl_down_sync(0xffffffffu, v, o);
                int   oi = __shfl_down_sync(0xffffffffu, idx, o);
                if (ov > v || (ov == v && oi < idx)) { v = ov; idx = oi; }
            }
            int   w  = __shfl_sync(0xffffffffu, idx, 0);
            float wv = __shfl_sync(0xffffffffu, v, 0);
            if (it == 0) mx = wv;
            if (w == lane)           sel0 = true;
            else if (w == lane + 32) sel1 = true;
        }

        float z0 = expf(l0 - mx), z1 = expf(l1 - mx);
        float zs = z0 + z1;
        for (int o = 16; o; o >>= 1) zs += __shfl_xor_sync(0xffffffffu, zs, o);
        float d0 = z0 / zs, d1 = z1 / zs;
        float ms = (sel0 ? d0 : 0.f) + (sel1 ? d1 : 0.f);
        for (int o = 16; o; o >>= 1) ms += __shfl_xor_sync(0xffffffffu, ms, o);
        float inv = 1.0f / (ms + 1e-9f);
        float p0 = sel0 ? d0 * inv : 0.f;
        float p1 = sel1 ? d1 * inv : 0.f;

        size_t bb = (size_t)(t0 + rr) * EE;
        out_mask[bb + lane]      = sel0 ? 1.f : 0.f;
        out_mask[bb + lane + 32] = sel1 ? 1.f : 0.f;
        out_prob[bb + lane]      = p0;
        out_prob[bb + lane + 32] = p1;
        out_lc[bb + lane]        = l0;
        out_lc[bb + lane + 32]   = l1;
        out_ls[bb + lane]        = l0;
        out_ls[bb + lane + 32]   = l1;
    }
}

// ---------------------------------------------------------------------------
extern "C" void kernel_launch(void* const* d_in, const int* in_sizes, int n_in,
                              void* d_out, int out_size) {
    const float* h     = (const float*)d_in[0];
    const float* proto = (const float*)d_in[1];
    float* out = (float*)d_out;
    int T = in_sizes[0] / DK;   // 16384

    pnorm_kernel<<<BN, 256>>>(proto);
    bsplit_kernel<<<512, 256>>>(proto);

    static bool attr_set = false;
    if (!attr_set) {
        cudaFuncSetAttribute(router_mma,
                             cudaFuncAttributeMaxDynamicSharedMemorySize,
                             SMEM_TOTAL);
        attr_set = true;
    }
    router_mma<<<T / BM, NTHREADS, SMEM_TOTAL>>>(h, proto, out, T);
}

// round 5
// speedup vs baseline: 2.4806x; 1.3454x over previous
#include <cuda_runtime.h>
#include <cuda_fp16.h>
#include <math.h>
#include <stdint.h>

// ---------------- problem constants ----------------
#define DK   4096
#define EE   64
#define TOPK 8
#define BM   128
#define BN   128
#define CHUNK 32                 // K floats per stage (two 16-K sub-chunks)
#define NSTAGE 128
#define NTHREADS 512

// ---------------- smem layout (bytes) ----------------
#define A_STAGE 16384            // [k16][plane][128 rows][32B]
#define B_STAGE 16384            // [k16][pass][n16][lane] uint4
#define OFF_A 0
#define OFF_B (2*A_STAGE)                 // 32768
#define OFF_SIMS (OFF_B + 4*B_STAGE)      // 98304
#define LDS_ 132
#define OFF_HSQ  (OFF_SIMS + 128*LDS_*4)  // 165888
#define OFF_INVH (OFF_HSQ + 512*4)
#define OFF_INVP (OFF_INVH + 128*4)
#define SMEM_TOTAL (OFF_INVP + 128*4)

__device__ float g_inv_pnorm[BN];
// B fragments: [kt(128)][k16(2)][pass(2)][n16(8)][lane(32)] -> uint4
__device__ uint4 g_bfrag[NSTAGE * 2 * 2 * 8 * 32];

// ---------------- helpers ----------------
__device__ __forceinline__ uint32_t smem_u32(const void* p) {
    uint32_t a;
    asm("{ .reg .u64 t; cvta.to.shared.u64 t, %1; cvt.u32.u64 %0, t; }" : "=r"(a) : "l"(p));
    return a;
}
__device__ __forceinline__ void ldm4(uint32_t* r, uint32_t addr) {
    asm volatile("ldmatrix.sync.aligned.m8n8.x4.shared.b16 {%0,%1,%2,%3}, [%4];"
        : "=r"(r[0]), "=r"(r[1]), "=r"(r[2]), "=r"(r[3]) : "r"(addr));
}
__device__ __forceinline__ uint4 lds128(uint32_t addr) {
    uint4 v;
    asm volatile("ld.shared.v4.u32 {%0,%1,%2,%3}, [%4];"
        : "=r"(v.x), "=r"(v.y), "=r"(v.z), "=r"(v.w) : "r"(addr));
    return v;
}
__device__ __forceinline__ void mma16816(float* c, const uint32_t* a, uint32_t b0, uint32_t b1) {
    asm volatile("mma.sync.aligned.m16n8k16.row.col.f32.f16.f16.f32 "
        "{%0,%1,%2,%3}, {%4,%5,%6,%7}, {%8,%9}, {%0,%1,%2,%3};"
        : "+f"(c[0]), "+f"(c[1]), "+f"(c[2]), "+f"(c[3])
        : "r"(a[0]), "r"(a[1]), "r"(a[2]), "r"(a[3]), "r"(b0), "r"(b1));
}
__device__ __forceinline__ void split2(float x, float y, uint32_t& uh, uint32_t& ul) {
    asm("cvt.rn.f16x2.f32 %0, %1, %2;" : "=r"(uh) : "f"(y), "f"(x));
    float lx = __half2float(__ushort_as_half((unsigned short)(uh & 0xffffu)));
    float ly = __half2float(__ushort_as_half((unsigned short)(uh >> 16)));
    float rx = x - lx, ry = y - ly;
    asm("cvt.rn.f16x2.f32 %0, %1, %2;" : "=r"(ul) : "f"(ry), "f"(rx));
}
#define CP_ASYNC16(dst, src) \
    asm volatile("cp.async.cg.shared.global [%0], [%1], 16;" :: "r"(dst), "l"(src))
#define CP_COMMIT() asm volatile("cp.async.commit_group;" ::: "memory")
#define CP_WAIT2()  asm volatile("cp.async.wait_group 2;"  ::: "memory")

// ---------------------------------------------------------------------------
// Kernel 1: inverse L2 norms of the 128 prototype rows
// ---------------------------------------------------------------------------
__global__ void pnorm_kernel(const float* __restrict__ proto) {
    int row = blockIdx.x;
    const float4* p = reinterpret_cast<const float4*>(proto + (size_t)row * DK);
    float s = 0.f;
    for (int i = threadIdx.x; i < DK / 4; i += blockDim.x) {
        float4 v = p[i];
        s += v.x * v.x + v.y * v.y + v.z * v.z + v.w * v.w;
    }
    for (int o = 16; o; o >>= 1) s += __shfl_down_sync(0xffffffffu, s, o);
    __shared__ float sm[8];
    if ((threadIdx.x & 31) == 0) sm[threadIdx.x >> 5] = s;
    __syncthreads();
    if (threadIdx.x == 0) {
        float t = 0.f;
        for (int i = 0; i < (int)(blockDim.x >> 5); i++) t += sm[i];
        g_inv_pnorm[row] = 1.0f / (sqrtf(t) + 1e-6f);
    }
}

// ---------------------------------------------------------------------------
// Kernel 2: pre-split proto into fp16 hi/lo fragments (validated layout)
// ---------------------------------------------------------------------------
__global__ void bsplit_kernel(const float* __restrict__ proto) {
    int idx  = blockIdx.x * blockDim.x + threadIdx.x;   // 131072 uint4
    int lane = idx & 31;
    int n16  = (idx >> 5) & 7;
    int pass = (idx >> 8) & 1;
    int k16  = (idx >> 9) & 1;
    int kt   = idx >> 10;
    int kt16 = kt * 2 + k16;
    uint32_t w[4];
#pragma unroll
    for (int r = 0; r < 4; r++) {
        int n  = n16 * 16 + ((r & 2) << 2) + (lane >> 2);
        int k0 = kt16 * 16 + (r & 1) * 8 + 2 * (lane & 3);
        float x = proto[(size_t)n * DK + k0];
        float y = proto[(size_t)n * DK + k0 + 1];
        uint32_t uh, ul;
        split2(x, y, uh, ul);
        w[r] = pass ? ul : uh;
    }
    g_bfrag[idx] = make_uint4(w[0], w[1], w[2], w[3]);
}

// ---------------------------------------------------------------------------
// Kernel 3: 3-pass split-fp16 mma GEMM, 512 threads, cp.async B pipeline
// ---------------------------------------------------------------------------
extern "C" __global__ void __launch_bounds__(NTHREADS, 1)
router_mma(const float* __restrict__ h, float* __restrict__ out, int T) {
    extern __shared__ char smem[];
    const uint32_t smem_u = smem_u32(smem);
    const int tid  = threadIdx.x;
    const int wid  = tid >> 5;
    const int lane = tid & 31;
    const int t0   = blockIdx.x * BM;

    if (tid < BN) ((float*)(smem + OFF_INVP))[tid] = g_inv_pnorm[tid];

    // A load/convert mapping: row = tid>>2, q = tid&3 -> 8 floats of the 32-chunk
    const int arow_g = tid >> 2;
    const int q      = tid & 3;
    const int k16q   = q >> 1;
    const int halfq  = q & 1;
    const float* ag = h + (size_t)(t0 + arow_g) * DK + q * 8;
    const uint32_t st_hi = OFF_A + (uint32_t)k16q * 8192u + (uint32_t)arow_g * 32u
                         + (uint32_t)((halfq ^ ((arow_g >> 2) & 1)) * 16);
    const uint32_t st_lo = st_hi + 4096u;

    // B cp.async mapping: 32B per thread per stage
    const char* bgp = (const char*)g_bfrag;
    const uint32_t bsts = OFF_B + (uint32_t)tid * 32u;

    // warp tile: 32 (M) x 32 (N)
    const int warp_m  = (wid >> 2) * 32;
    const int warp_n4 = (wid & 3) * 2;

    uint32_t aoff[2];
#pragma unroll
    for (int mi = 0; mi < 2; mi++) {
        int ar = warp_m + mi * 16 + ((lane >> 3) & 1) * 8 + (lane & 7);
        int kh = lane >> 4;
        aoff[mi] = (uint32_t)ar * 32u + (uint32_t)((kh ^ ((ar >> 2) & 1)) * 16);
    }
    const uint32_t boff = (uint32_t)warp_n4 * 512u + (uint32_t)lane * 16u;

    float acc[2][4][4];
#pragma unroll
    for (int a = 0; a < 2; a++)
#pragma unroll
        for (int b = 0; b < 4; b++)
#pragma unroll
            for (int c = 0; c < 4; c++) acc[a][b][c] = 0.f;

    float hsum = 0.f;
    float4 av0, av1;

    // ---- prologue: B stages 0..2 via cp.async; A chunk 0 convert+store ----
#pragma unroll
    for (int s = 0; s < 3; s++) {
        uint32_t d = smem_u + bsts + (uint32_t)s * B_STAGE;
        const char* g = bgp + (size_t)s * B_STAGE + (size_t)tid * 32;
        CP_ASYNC16(d, g); CP_ASYNC16(d + 16, g + 16);
        CP_COMMIT();
    }
    av0 = ((const float4*)ag)[0]; av1 = ((const float4*)ag)[1];
    {
        uint32_t uh[4], ul[4];
        split2(av0.x, av0.y, uh[0], ul[0]);
        split2(av0.z, av0.w, uh[1], ul[1]);
        split2(av1.x, av1.y, uh[2], ul[2]);
        split2(av1.z, av1.w, uh[3], ul[3]);
        hsum += av0.x*av0.x + av0.y*av0.y + av0.z*av0.z + av0.w*av0.w
              + av1.x*av1.x + av1.y*av1.y + av1.z*av1.z + av1.w*av1.w;
        *(uint4*)(smem + st_hi) = make_uint4(uh[0], uh[1], uh[2], uh[3]);
        *(uint4*)(smem + st_lo) = make_uint4(ul[0], ul[1], ul[2], ul[3]);
    }
    av0 = ((const float4*)(ag + CHUNK))[0];
    av1 = ((const float4*)(ag + CHUNK))[1];
    CP_WAIT2();
    __syncthreads();

    // ---- main loop: one sync per 32-K stage ----
#pragma unroll 1
    for (int kt = 0; kt < NSTAGE; ++kt) {
        const uint32_t abase = smem_u + OFF_A + (uint32_t)(kt & 1) * A_STAGE;
        const uint32_t bbase = smem_u + OFF_B + (uint32_t)(kt & 3) * B_STAGE;

        // ================= k16 = 0 =================
        uint32_t A[2][4];
        ldm4(A[0], abase + aoff[0]);
        ldm4(A[1], abase + aoff[1]);
        uint4 b0 = lds128(bbase + boff);              // hi tile 0
        uint4 b1 = lds128(bbase + boff + 512);        // hi tile 1
#pragma unroll
        for (int mi = 0; mi < 2; mi++) {              // A_hi x B_hi
            mma16816(acc[mi][0], A[mi], b0.x, b0.y);
            mma16816(acc[mi][1], A[mi], b0.z, b0.w);
            mma16816(acc[mi][2], A[mi], b1.x, b1.y);
            mma16816(acc[mi][3], A[mi], b1.z, b1.w);
        }
        // issue B(kt+3) cp.async
        {
            int ks = kt + 3;
            if (ks < NSTAGE) {
                uint32_t d = smem_u + bsts + (uint32_t)(ks & 3) * B_STAGE;
                const char* g = bgp + (size_t)ks * B_STAGE + (size_t)tid * 32;
                CP_ASYNC16(d, g); CP_ASYNC16(d + 16, g + 16);
            }
            CP_COMMIT();
        }
        {
            uint4 b2 = lds128(bbase + boff + 8 * 512);    // lo tile 0
            uint4 b3 = lds128(bbase + boff + 9 * 512);    // lo tile 1
#pragma unroll
            for (int mi = 0; mi < 2; mi++) {              // A_hi x B_lo
                mma16816(acc[mi][0], A[mi], b2.x, b2.y);
                mma16816(acc[mi][1], A[mi], b2.z, b2.w);
                mma16816(acc[mi][2], A[mi], b3.x, b3.y);
                mma16816(acc[mi][3], A[mi], b3.z, b3.w);
            }
        }
        ldm4(A[0], abase + 4096u + aoff[0]);              // A_lo
        ldm4(A[1], abase + 4096u + aoff[1]);
#pragma unroll
        for (int mi = 0; mi < 2; mi++) {                  // A_lo x B_hi
            mma16816(acc[mi][0], A[mi], b0.x, b0.y);
            mma16816(acc[mi][1], A[mi], b0.z, b0.w);
            mma16816(acc[mi][2], A[mi], b1.x, b1.y);
            mma16816(acc[mi][3], A[mi], b1.z, b1.w);
        }

        // convert + store A chunk kt+1 into the other buffer
        if (kt + 1 < NSTAGE) {
            char* stg = smem + ((kt + 1) & 1) * A_STAGE;
            uint32_t uh[4], ul[4];
            split2(av0.x, av0.y, uh[0], ul[0]);
            split2(av0.z, av0.w, uh[1], ul[1]);
            split2(av1.x, av1.y, uh[2], ul[2]);
            split2(av1.z, av1.w, uh[3], ul[3]);
            hsum += av0.x*av0.x + av0.y*av0.y + av0.z*av0.z + av0.w*av0.w
                  + av1.x*av1.x + av1.y*av1.y + av1.z*av1.z + av1.w*av1.w;
            *(uint4*)(stg + st_hi) = make_uint4(uh[0], uh[1], uh[2], uh[3]);
            *(uint4*)(stg + st_lo) = make_uint4(ul[0], ul[1], ul[2], ul[3]);
        }

        // ================= k16 = 1 =================
        ldm4(A[0], abase + 8192u + aoff[0]);
        ldm4(A[1], abase + 8192u + aoff[1]);
        b0 = lds128(bbase + boff + 16 * 512);
        b1 = lds128(bbase + boff + 17 * 512);
#pragma unroll
        for (int mi = 0; mi < 2; mi++) {
            mma16816(acc[mi][0], A[mi], b0.x, b0.y);
            mma16816(acc[mi][1], A[mi], b0.z, b0.w);
            mma16816(acc[mi][2], A[mi], b1.x, b1.y);
            mma16816(acc[mi][3], A[mi], b1.z, b1.w);
        }
        // prefetch A chunk kt+2
        {
            int ka = (kt + 2 < NSTAGE) ? kt + 2 : NSTAGE - 1;
            av0 = ((const float4*)(ag + (size_t)ka * CHUNK))[0];
            av1 = ((const float4*)(ag + (size_t)ka * CHUNK))[1];
        }
        {
            uint4 b2 = lds128(bbase + boff + 24 * 512);
            uint4 b3 = lds128(bbase + boff + 25 * 512);
#pragma unroll
            for (int mi = 0; mi < 2; mi++) {
                mma16816(acc[mi][0], A[mi], b2.x, b2.y);
                mma16816(acc[mi][1], A[mi], b2.z, b2.w);
                mma16816(acc[mi][2], A[mi], b3.x, b3.y);
                mma16816(acc[mi][3], A[mi], b3.z, b3.w);
            }
        }
        ldm4(A[0], abase + 8192u + 4096u + aoff[0]);
        ldm4(A[1], abase + 8192u + 4096u + aoff[1]);
#pragma unroll
        for (int mi = 0; mi < 2; mi++) {
            mma16816(acc[mi][0], A[mi], b0.x, b0.y);
            mma16816(acc[mi][1], A[mi], b0.z, b0.w);
            mma16816(acc[mi][2], A[mi], b1.x, b1.y);
            mma16816(acc[mi][3], A[mi], b1.z, b1.w);
        }

        CP_WAIT2();
        __syncthreads();
    }

    // ---- norms ----
    ((float*)(smem + OFF_HSQ))[tid] = hsum;
    __syncthreads();
    if (tid < BM) {
        const float* hsq = (const float*)(smem + OFF_HSQ);
        float s = hsq[4 * tid] + hsq[4 * tid + 1] + hsq[4 * tid + 2] + hsq[4 * tid + 3];
        ((float*)(smem + OFF_INVH))[tid] = 1.0f / (sqrtf(s) + 1e-6f);
    }
    __syncthreads();

    // ---- accumulators -> scaled cosine sims in smem ----
    {
        const float* invh = (const float*)(smem + OFF_INVH);
        const float* invp = (const float*)(smem + OFF_INVP);
        float* sims = (float*)(smem + OFF_SIMS);
        const int warp_n = (wid & 3) * 32;
        int lr = lane >> 2, lc = (lane & 3) * 2;
#pragma unroll
        for (int mi = 0; mi < 2; mi++) {
            int row = warp_m + mi * 16 + lr;
            float ih0 = invh[row], ih1 = invh[row + 8];
#pragma unroll
            for (int nf = 0; nf < 4; nf++) {
                int col = warp_n + nf * 8 + lc;
                float ip0 = invp[col], ip1 = invp[col + 1];
                sims[row * LDS_ + col]           = acc[mi][nf][0] * ih0 * ip0;
                sims[row * LDS_ + col + 1]       = acc[mi][nf][1] * ih0 * ip1;
                sims[(row + 8) * LDS_ + col]     = acc[mi][nf][2] * ih1 * ip0;
                sims[(row + 8) * LDS_ + col + 1] = acc[mi][nf][3] * ih1 * ip1;
            }
        }
    }
    __syncthreads();

    // ---- per-token router: 16 warps, 8 rows each ----
    const float* sims = (const float*)(smem + OFF_SIMS);
    float* out_mask = out;
    float* out_prob = out + (size_t)T * EE;
    float* out_lc   = out + (size_t)2 * T * EE;
    float* out_ls   = out + (size_t)3 * T * EE;

    for (int rr = wid; rr < BM; rr += 16) {
        const float* srow = &sims[rr * LDS_];
        float l0, l1;
        {
            float s0 = srow[2 * lane], s1 = srow[2 * lane + 1];
            float m = fmaxf(s0, s1);
            l0 = 10.0f * (m + logf(expf(s0 - m) + expf(s1 - m)));
            s0 = srow[64 + 2 * lane]; s1 = srow[64 + 2 * lane + 1];
            m = fmaxf(s0, s1);
            l1 = 10.0f * (m + logf(expf(s0 - m) + expf(s1 - m)));
        }

        bool sel0 = false, sel1 = false;
        float mx = -INFINITY;
#pragma unroll
        for (int it = 0; it < TOPK; ++it) {
            float v0 = sel0 ? -INFINITY : l0;
            float v1 = sel1 ? -INFINITY : l1;
            float v; int idx;
            if (v0 >= v1) { v = v0; idx = lane; }
            else          { v = v1; idx = lane + 32; }
            for (int o = 16; o; o >>= 1) {
                float ov = __shfl_down_sync(0xffffffffu, v, o);
                int   oi = __shfl_down_sync(0xffffffffu, idx, o);
                if (ov > v || (ov == v && oi < idx)) { v = ov; idx = oi; }
            }
            int   w  = __shfl_sync(0xffffffffu, idx, 0);
            float wv = __shfl_sync(0xffffffffu, v, 0);
            if (it == 0) mx = wv;
            if (w == lane)           sel0 = true;
            else if (w == lane + 32) sel1 = true;
        }

        float z0 = expf(l0 - mx), z1 = expf(l1 - mx);
        float zs = z0 + z1;
        for (int o = 16; o; o >>= 1) zs += __shfl_xor_sync(0xffffffffu, zs, o);
        float d0 = z0 / zs, d1 = z1 / zs;
        float ms = (sel0 ? d0 : 0.f) + (sel1 ? d1 : 0.f);
        for (int o = 16; o; o >>= 1) ms += __shfl_xor_sync(0xffffffffu, ms, o);
        float inv = 1.0f / (ms + 1e-9f);
        float p0 = sel0 ? d0 * inv : 0.f;
        float p1 = sel1 ? d1 * inv : 0.f;

        size_t bb = (size_t)(t0 + rr) * EE;
        out_mask[bb + lane]      = sel0 ? 1.f : 0.f;
        out_mask[bb + lane + 32] = sel1 ? 1.f : 0.f;
        out_prob[bb + lane]      = p0;
        out_prob[bb + lane + 32] = p1;
        out_lc[bb + lane]        = l0;
        out_lc[bb + lane + 32]   = l1;
        out_ls[bb + lane]        = l0;
        out_ls[bb + lane + 32]   = l1;
    }
}

// ---------------------------------------------------------------------------
extern "C" void kernel_launch(void* const* d_in, const int* in_sizes, int n_in,
                              void* d_out, int out_size) {
    const float* h     = (const float*)d_in[0];
    const float* proto = (const float*)d_in[1];
    float* out = (float*)d_out;
    int T = in_sizes[0] / DK;   // 16384

    pnorm_kernel<<<BN, 256>>>(proto);
    bsplit_kernel<<<512, 256>>>(proto);

    static bool attr_set = false;
    if (!attr_set) {
        cudaFuncSetAttribute(router_mma,
                             cudaFuncAttributeMaxDynamicSharedMemorySize,
                             SMEM_TOTAL);
        attr_set = true;
    }
    router_mma<<<T / BM, NTHREADS, SMEM_TOTAL>>>(h, out, T);
}

// round 6
// speedup vs baseline: 2.7759x; 1.1190x over previous
#include <cuda_runtime.h>
#include <cuda_fp16.h>
#include <math.h>
#include <stdint.h>

// ---------------- problem constants ----------------
#define DK   4096
#define EE   64
#define TOPK 8
#define BM   128
#define BN   128
#define CHUNK 32                 // K floats per stage (two 16-K sub-chunks)
#define NSTAGE 128
#define NTHREADS 512

// ---------------- smem layout (bytes) ----------------
#define A_STAGE 16384            // [k16][plane][128 rows][32B]
#define B_STAGE 16384            // [k16][pass][n16][lane] uint4
#define OFF_A 0
#define OFF_B (2*A_STAGE)                 // 32768
#define OFF_SIMS (OFF_B + 4*B_STAGE)      // 98304
#define LDS_ 132
#define OFF_HSQ  (OFF_SIMS + 128*LDS_*4)  // 165888
#define OFF_INVH (OFF_HSQ + 512*4)
#define OFF_INVP (OFF_INVH + 128*4)
#define SMEM_TOTAL (OFF_INVP + 128*4)

__device__ float g_inv_pnorm[BN];
// B fragments: [kt(128)][k16(2)][pass(2)][n16(8)][lane(32)] -> uint4
__device__ uint4 g_bfrag[NSTAGE * 2 * 2 * 8 * 32];

// ---------------- helpers ----------------
__device__ __forceinline__ uint32_t smem_u32(const void* p) {
    uint32_t a;
    asm("{ .reg .u64 t; cvta.to.shared.u64 t, %1; cvt.u32.u64 %0, t; }" : "=r"(a) : "l"(p));
    return a;
}
__device__ __forceinline__ void ldm4(uint32_t* r, uint32_t addr) {
    asm volatile("ldmatrix.sync.aligned.m8n8.x4.shared.b16 {%0,%1,%2,%3}, [%4];"
        : "=r"(r[0]), "=r"(r[1]), "=r"(r[2]), "=r"(r[3]) : "r"(addr));
}
__device__ __forceinline__ uint4 lds128(uint32_t addr) {
    uint4 v;
    asm volatile("ld.shared.v4.u32 {%0,%1,%2,%3}, [%4];"
        : "=r"(v.x), "=r"(v.y), "=r"(v.z), "=r"(v.w) : "r"(addr));
    return v;
}
__device__ __forceinline__ void mma16816(float* c, const uint32_t* a, uint32_t b0, uint32_t b1) {
    asm volatile("mma.sync.aligned.m16n8k16.row.col.f32.f16.f16.f32 "
        "{%0,%1,%2,%3}, {%4,%5,%6,%7}, {%8,%9}, {%0,%1,%2,%3};"
        : "+f"(c[0]), "+f"(c[1]), "+f"(c[2]), "+f"(c[3])
        : "r"(a[0]), "r"(a[1]), "r"(a[2]), "r"(a[3]), "r"(b0), "r"(b1));
}
__device__ __forceinline__ void split2(float x, float y, uint32_t& uh, uint32_t& ul) {
    asm("cvt.rn.f16x2.f32 %0, %1, %2;" : "=r"(uh) : "f"(y), "f"(x));
    float lx = __half2float(__ushort_as_half((unsigned short)(uh & 0xffffu)));
    float ly = __half2float(__ushort_as_half((unsigned short)(uh >> 16)));
    float rx = x - lx, ry = y - ly;
    asm("cvt.rn.f16x2.f32 %0, %1, %2;" : "=r"(ul) : "f"(ry), "f"(rx));
}
#define CP_ASYNC16(dst, src) \
    asm volatile("cp.async.cg.shared.global [%0], [%1], 16;" :: "r"(dst), "l"(src))
#define CP_COMMIT() asm volatile("cp.async.commit_group;" ::: "memory")
#define CP_WAIT1()  asm volatile("cp.async.wait_group 1;"  ::: "memory")

// ---------------------------------------------------------------------------
// Kernel 1: inverse L2 norms of the 128 prototype rows
// ---------------------------------------------------------------------------
__global__ void pnorm_kernel(const float* __restrict__ proto) {
    int row = blockIdx.x;
    const float4* p = reinterpret_cast<const float4*>(proto + (size_t)row * DK);
    float s = 0.f;
    for (int i = threadIdx.x; i < DK / 4; i += blockDim.x) {
        float4 v = p[i];
        s += v.x * v.x + v.y * v.y + v.z * v.z + v.w * v.w;
    }
    for (int o = 16; o; o >>= 1) s += __shfl_down_sync(0xffffffffu, s, o);
    __shared__ float sm[8];
    if ((threadIdx.x & 31) == 0) sm[threadIdx.x >> 5] = s;
    __syncthreads();
    if (threadIdx.x == 0) {
        float t = 0.f;
        for (int i = 0; i < (int)(blockDim.x >> 5); i++) t += sm[i];
        g_inv_pnorm[row] = 1.0f / (sqrtf(t) + 1e-6f);
    }
}

// ---------------------------------------------------------------------------
// Kernel 2: pre-split proto into fp16 hi/lo fragments (validated layout)
// ---------------------------------------------------------------------------
__global__ void bsplit_kernel(const float* __restrict__ proto) {
    int idx  = blockIdx.x * blockDim.x + threadIdx.x;   // 131072 uint4
    int lane = idx & 31;
    int n16  = (idx >> 5) & 7;
    int pass = (idx >> 8) & 1;
    int k16  = (idx >> 9) & 1;
    int kt   = idx >> 10;
    int kt16 = kt * 2 + k16;
    uint32_t w[4];
#pragma unroll
    for (int r = 0; r < 4; r++) {
        int n  = n16 * 16 + ((r & 2) << 2) + (lane >> 2);
        int k0 = kt16 * 16 + (r & 1) * 8 + 2 * (lane & 3);
        float x = proto[(size_t)n * DK + k0];
        float y = proto[(size_t)n * DK + k0 + 1];
        uint32_t uh, ul;
        split2(x, y, uh, ul);
        w[r] = pass ? ul : uh;
    }
    g_bfrag[idx] = make_uint4(w[0], w[1], w[2], w[3]);
}

// ---------------------------------------------------------------------------
// Kernel 3: 3-pass split-fp16 mma GEMM, hoisted operands + pre-barrier B preload
// ---------------------------------------------------------------------------
extern "C" __global__ void __launch_bounds__(NTHREADS, 1)
router_mma(const float* __restrict__ h, float* __restrict__ out, int T) {
    extern __shared__ char smem[];
    const uint32_t smem_u = smem_u32(smem);
    const int tid  = threadIdx.x;
    const int wid  = tid >> 5;
    const int lane = tid & 31;
    const int t0   = blockIdx.x * BM;

    if (tid < BN) ((float*)(smem + OFF_INVP))[tid] = g_inv_pnorm[tid];

    // A load/convert mapping: row = tid>>2, q = tid&3 -> 8 floats of the 32-chunk
    const int arow_g = tid >> 2;
    const int q      = tid & 3;
    const int k16q   = q >> 1;
    const int halfq  = q & 1;
    const float* ag = h + (size_t)(t0 + arow_g) * DK + q * 8;
    const uint32_t st_hi = OFF_A + (uint32_t)k16q * 8192u + (uint32_t)arow_g * 32u
                         + (uint32_t)((halfq ^ ((arow_g >> 2) & 1)) * 16);
    const uint32_t st_lo = st_hi + 4096u;

    // B cp.async mapping: 32B per thread per stage
    const char* bgp = (const char*)g_bfrag;
    const uint32_t bsts = OFF_B + (uint32_t)tid * 32u;

    // warp tile: 32 (M) x 32 (N)
    const int warp_m  = (wid >> 2) * 32;
    const int warp_n4 = (wid & 3) * 2;

    uint32_t aoff[2];
#pragma unroll
    for (int mi = 0; mi < 2; mi++) {
        int ar = warp_m + mi * 16 + ((lane >> 3) & 1) * 8 + (lane & 7);
        int kh = lane >> 4;
        aoff[mi] = (uint32_t)ar * 32u + (uint32_t)((kh ^ ((ar >> 2) & 1)) * 16);
    }
    const uint32_t boff = (uint32_t)warp_n4 * 512u + (uint32_t)lane * 16u;

    float acc[2][4][4];
#pragma unroll
    for (int a = 0; a < 2; a++)
#pragma unroll
        for (int b = 0; b < 4; b++)
#pragma unroll
            for (int c = 0; c < 4; c++) acc[a][b][c] = 0.f;

    float hsum = 0.f;
    float4 av0, av1;

    // ---- prologue: B stages 0..2 via cp.async; A chunk 0 convert+store ----
#pragma unroll
    for (int s = 0; s < 3; s++) {
        uint32_t d = smem_u + bsts + (uint32_t)s * B_STAGE;
        const char* g = bgp + (size_t)s * B_STAGE + (size_t)tid * 32;
        CP_ASYNC16(d, g); CP_ASYNC16(d + 16, g + 16);
        CP_COMMIT();
    }
    av0 = ((const float4*)ag)[0]; av1 = ((const float4*)ag)[1];
    {
        uint32_t uh[4], ul[4];
        split2(av0.x, av0.y, uh[0], ul[0]);
        split2(av0.z, av0.w, uh[1], ul[1]);
        split2(av1.x, av1.y, uh[2], ul[2]);
        split2(av1.z, av1.w, uh[3], ul[3]);
        hsum += av0.x*av0.x + av0.y*av0.y + av0.z*av0.z + av0.w*av0.w
              + av1.x*av1.x + av1.y*av1.y + av1.z*av1.z + av1.w*av1.w;
        *(uint4*)(smem + st_hi) = make_uint4(uh[0], uh[1], uh[2], uh[3]);
        *(uint4*)(smem + st_lo) = make_uint4(ul[0], ul[1], ul[2], ul[3]);
    }
    av0 = ((const float4*)(ag + CHUNK))[0];
    av1 = ((const float4*)(ag + CHUNK))[1];
    CP_WAIT1();
    __syncthreads();

    // preload stage-0 k16=0 B fragments into registers
    uint4 nbh0, nbh1, nbl0, nbl1;
    {
        uint32_t nbb = smem_u + OFF_B;
        nbh0 = lds128(nbb + boff);
        nbh1 = lds128(nbb + boff + 512);
        nbl0 = lds128(nbb + boff + 4096);
        nbl1 = lds128(nbb + boff + 4096 + 512);
    }

    // ---- main loop: one sync per 32-K stage ----
#pragma unroll 1
    for (int kt = 0; kt < NSTAGE; ++kt) {
        const uint32_t abase = smem_u + OFF_A + (uint32_t)(kt & 1) * A_STAGE;
        const uint32_t bbase = smem_u + OFF_B + (uint32_t)(kt & 3) * B_STAGE;

        // ================= k16 = 0 : all operands upfront =================
        uint32_t Ah[2][4], Al[2][4];
        ldm4(Ah[0], abase + aoff[0]);
        ldm4(Ah[1], abase + aoff[1]);
        ldm4(Al[0], abase + 4096u + aoff[0]);
        ldm4(Al[1], abase + 4096u + aoff[1]);
        uint4 bh0 = nbh0, bh1 = nbh1, bl0 = nbl0, bl1 = nbl1;

#pragma unroll
        for (int mi = 0; mi < 2; mi++) {              // A_hi x B_hi
            mma16816(acc[mi][0], Ah[mi], bh0.x, bh0.y);
            mma16816(acc[mi][1], Ah[mi], bh0.z, bh0.w);
            mma16816(acc[mi][2], Ah[mi], bh1.x, bh1.y);
            mma16816(acc[mi][3], Ah[mi], bh1.z, bh1.w);
        }
        // issue B(kt+3) cp.async
        {
            int ks = kt + 3;
            if (ks < NSTAGE) {
                uint32_t d = smem_u + bsts + (uint32_t)(ks & 3) * B_STAGE;
                const char* g = bgp + (size_t)ks * B_STAGE + (size_t)tid * 32;
                CP_ASYNC16(d, g); CP_ASYNC16(d + 16, g + 16);
            }
            CP_COMMIT();
        }
#pragma unroll
        for (int mi = 0; mi < 2; mi++) {              // A_hi x B_lo
            mma16816(acc[mi][0], Ah[mi], bl0.x, bl0.y);
            mma16816(acc[mi][1], Ah[mi], bl0.z, bl0.w);
            mma16816(acc[mi][2], Ah[mi], bl1.x, bl1.y);
            mma16816(acc[mi][3], Ah[mi], bl1.z, bl1.w);
        }

        // convert + store A chunk kt+1 into the other buffer
        if (kt + 1 < NSTAGE) {
            char* stg = smem + ((kt + 1) & 1) * A_STAGE;
            uint32_t uh[4], ul[4];
            split2(av0.x, av0.y, uh[0], ul[0]);
            split2(av0.z, av0.w, uh[1], ul[1]);
            split2(av1.x, av1.y, uh[2], ul[2]);
            split2(av1.z, av1.w, uh[3], ul[3]);
            hsum += av0.x*av0.x + av0.y*av0.y + av0.z*av0.z + av0.w*av0.w
                  + av1.x*av1.x + av1.y*av1.y + av1.z*av1.z + av1.w*av1.w;
            *(uint4*)(stg + st_hi) = make_uint4(uh[0], uh[1], uh[2], uh[3]);
            *(uint4*)(stg + st_lo) = make_uint4(ul[0], ul[1], ul[2], ul[3]);
        }

#pragma unroll
        for (int mi = 0; mi < 2; mi++) {              // A_lo x B_hi
            mma16816(acc[mi][0], Al[mi], bh0.x, bh0.y);
            mma16816(acc[mi][1], Al[mi], bh0.z, bh0.w);
            mma16816(acc[mi][2], Al[mi], bh1.x, bh1.y);
            mma16816(acc[mi][3], Al[mi], bh1.z, bh1.w);
        }

        // ================= k16 = 1 : all operands upfront =================
        ldm4(Ah[0], abase + 8192u + aoff[0]);
        ldm4(Ah[1], abase + 8192u + aoff[1]);
        ldm4(Al[0], abase + 8192u + 4096u + aoff[0]);
        ldm4(Al[1], abase + 8192u + 4096u + aoff[1]);
        bh0 = lds128(bbase + 8192u + boff);
        bh1 = lds128(bbase + 8192u + boff + 512);
        bl0 = lds128(bbase + 8192u + boff + 4096);
        bl1 = lds128(bbase + 8192u + boff + 4096 + 512);

#pragma unroll
        for (int mi = 0; mi < 2; mi++) {              // A_hi x B_hi
            mma16816(acc[mi][0], Ah[mi], bh0.x, bh0.y);
            mma16816(acc[mi][1], Ah[mi], bh0.z, bh0.w);
            mma16816(acc[mi][2], Ah[mi], bh1.x, bh1.y);
            mma16816(acc[mi][3], Ah[mi], bh1.z, bh1.w);
        }
        // prefetch A chunk kt+2
        {
            int ka = (kt + 2 < NSTAGE) ? kt + 2 : NSTAGE - 1;
            av0 = ((const float4*)(ag + (size_t)ka * CHUNK))[0];
            av1 = ((const float4*)(ag + (size_t)ka * CHUNK))[1];
        }
#pragma unroll
        for (int mi = 0; mi < 2; mi++) {              // A_hi x B_lo
            mma16816(acc[mi][0], Ah[mi], bl0.x, bl0.y);
            mma16816(acc[mi][1], Ah[mi], bl0.z, bl0.w);
            mma16816(acc[mi][2], Ah[mi], bl1.x, bl1.y);
            mma16816(acc[mi][3], Ah[mi], bl1.z, bl1.w);
        }
#pragma unroll
        for (int mi = 0; mi < 2; mi++) {              // A_lo x B_hi
            mma16816(acc[mi][0], Al[mi], bh0.x, bh0.y);
            mma16816(acc[mi][1], Al[mi], bh0.z, bh0.w);
            mma16816(acc[mi][2], Al[mi], bh1.x, bh1.y);
            mma16816(acc[mi][3], Al[mi], bh1.z, bh1.w);
        }

        CP_WAIT1();
        // preload next-stage k16=0 B fragments (visible since last sync)
        {
            uint32_t nbb = smem_u + OFF_B + (uint32_t)((kt + 1) & 3) * B_STAGE;
            nbh0 = lds128(nbb + boff);
            nbh1 = lds128(nbb + boff + 512);
            nbl0 = lds128(nbb + boff + 4096);
            nbl1 = lds128(nbb + boff + 4096 + 512);
        }
        __syncthreads();
    }

    // ---- norms ----
    ((float*)(smem + OFF_HSQ))[tid] = hsum;
    __syncthreads();
    if (tid < BM) {
        const float* hsq = (const float*)(smem + OFF_HSQ);
        float s = hsq[4 * tid] + hsq[4 * tid + 1] + hsq[4 * tid + 2] + hsq[4 * tid + 3];
        ((float*)(smem + OFF_INVH))[tid] = 1.0f / (sqrtf(s) + 1e-6f);
    }
    __syncthreads();

    // ---- accumulators -> scaled cosine sims in smem ----
    {
        const float* invh = (const float*)(smem + OFF_INVH);
        const float* invp = (const float*)(smem + OFF_INVP);
        float* sims = (float*)(smem + OFF_SIMS);
        const int warp_n = (wid & 3) * 32;
        int lr = lane >> 2, lc = (lane & 3) * 2;
#pragma unroll
        for (int mi = 0; mi < 2; mi++) {
            int row = warp_m + mi * 16 + lr;
            float ih0 = invh[row], ih1 = invh[row + 8];
#pragma unroll
            for (int nf = 0; nf < 4; nf++) {
                int col = warp_n + nf * 8 + lc;
                float ip0 = invp[col], ip1 = invp[col + 1];
                sims[row * LDS_ + col]           = acc[mi][nf][0] * ih0 * ip0;
                sims[row * LDS_ + col + 1]       = acc[mi][nf][1] * ih0 * ip1;
                sims[(row + 8) * LDS_ + col]     = acc[mi][nf][2] * ih1 * ip0;
                sims[(row + 8) * LDS_ + col + 1] = acc[mi][nf][3] * ih1 * ip1;
            }
        }
    }
    __syncthreads();

    // ---- per-token router: 16 warps, 8 rows each ----
    const float* sims = (const float*)(smem + OFF_SIMS);
    float* out_mask = out;
    float* out_prob = out + (size_t)T * EE;
    float* out_lc   = out + (size_t)2 * T * EE;
    float* out_ls   = out + (size_t)3 * T * EE;

    for (int rr = wid; rr < BM; rr += 16) {
        const float* srow = &sims[rr * LDS_];
        float l0, l1;
        {
            float s0 = srow[2 * lane], s1 = srow[2 * lane + 1];
            float m = fmaxf(s0, s1);
            l0 = 10.0f * (m + logf(expf(s0 - m) + expf(s1 - m)));
            s0 = srow[64 + 2 * lane]; s1 = srow[64 + 2 * lane + 1];
            m = fmaxf(s0, s1);
            l1 = 10.0f * (m + logf(expf(s0 - m) + expf(s1 - m)));
        }

        bool sel0 = false, sel1 = false;
        float mx = -INFINITY;
#pragma unroll
        for (int it = 0; it < TOPK; ++it) {
            float v0 = sel0 ? -INFINITY : l0;
            float v1 = sel1 ? -INFINITY : l1;
            float v; int idx;
            if (v0 >= v1) { v = v0; idx = lane; }
            else          { v = v1; idx = lane + 32; }
            for (int o = 16; o; o >>= 1) {
                float ov = __shfl_down_sync(0xffffffffu, v, o);
                int   oi = __shfl_down_sync(0xffffffffu, idx, o);
                if (ov > v || (ov == v && oi < idx)) { v = ov; idx = oi; }
            }
            int   w  = __shfl_sync(0xffffffffu, idx, 0);
            float wv = __shfl_sync(0xffffffffu, v, 0);
            if (it == 0) mx = wv;
            if (w == lane)           sel0 = true;
            else if (w == lane + 32) sel1 = true;
        }

        float z0 = expf(l0 - mx), z1 = expf(l1 - mx);
        float zs = z0 + z1;
        for (int o = 16; o; o >>= 1) zs += __shfl_xor_sync(0xffffffffu, zs, o);
        float d0 = z0 / zs, d1 = z1 / zs;
        float ms = (sel0 ? d0 : 0.f) + (sel1 ? d1 : 0.f);
        for (int o = 16; o; o >>= 1) ms += __shfl_xor_sync(0xffffffffu, ms, o);
        float inv = 1.0f / (ms + 1e-9f);
        float p0 = sel0 ? d0 * inv : 0.f;
        float p1 = sel1 ? d1 * inv : 0.f;

        size_t bb = (size_t)(t0 + rr) * EE;
        out_mask[bb + lane]      = sel0 ? 1.f : 0.f;
        out_mask[bb + lane + 32] = sel1 ? 1.f : 0.f;
        out_prob[bb + lane]      = p0;
        out_prob[bb + lane + 32] = p1;
        out_lc[bb + lane]        = l0;
        out_lc[bb + lane + 32]   = l1;
        out_ls[bb + lane]        = l0;
        out_ls[bb + lane + 32]   = l1;
    }
}

// ---------------------------------------------------------------------------
extern "C" void kernel_launch(void* const* d_in, const int* in_sizes, int n_in,
                              void* d_out, int out_size) {
    const float* h     = (const float*)d_in[0];
    const float* proto = (const float*)d_in[1];
    float* out = (float*)d_out;
    int T = in_sizes[0] / DK;   // 16384

    pnorm_kernel<<<BN, 256>>>(proto);
    bsplit_kernel<<<512, 256>>>(proto);

    static bool attr_set = false;
    if (!attr_set) {
        cudaFuncSetAttribute(router_mma,
                             cudaFuncAttributeMaxDynamicSharedMemorySize,
                             SMEM_TOTAL);
        attr_set = true;
    }
    router_mma<<<T / BM, NTHREADS, SMEM_TOTAL>>>(h, out, T);
}